// round 8
// baseline (speedup 1.0000x reference)
#include <cuda_runtime.h>

#define HID 8192
#define BATCH 512
#define NIN 16
#define RANK 8
#define NOUT 4
#define GRID 256
#define TPB 256

// u partials: two H-halves, folded in phase 2 (fixed order => deterministic)
__device__ float g_u_part[2][BATCH * RANK];
// per-j-tile readout partials, folded in phase 3 (fixed order => deterministic)
__device__ float g_out_part[32][BATCH * NOUT];
__device__ unsigned int g_bar;   // monotone ticket counter, never reset (replay-safe)

typedef unsigned long long ull;

__device__ __forceinline__ void ffma2(ull& d, ull a, ull b) {
    asm("fma.rn.f32x2 %0, %1, %2, %0;" : "+l"(d) : "l"(a), "l"(b));
}
__device__ __forceinline__ void unpack2(float& lo, float& hi, ull v) {
    asm("mov.b64 {%0, %1}, %2;" : "=f"(lo), "=f"(hi) : "l"(v));
}

__device__ __forceinline__ void grid_barrier() {
    __syncthreads();
    if (threadIdx.x == 0) {
        __threadfence();
        unsigned int old = atomicAdd(&g_bar, 1u);
        unsigned int target = (old / GRID + 1u) * GRID;
        while ((int)(*(volatile unsigned int*)&g_bar - target) < 0)
            __nanosleep(32);
        __threadfence();
    }
    __syncthreads();
}

__global__ void __launch_bounds__(TPB, 2) k_fused(const float* __restrict__ input,
                                                  const float* __restrict__ hidden,
                                                  const float* __restrict__ Win,
                                                  const float* __restrict__ L,
                                                  const float* __restrict__ R,
                                                  const float* __restrict__ Wout,
                                                  float* __restrict__ nh,
                                                  float* __restrict__ out) {
    const int t = threadIdx.x;
    const int lane = t & 31, w = t >> 5;

    __shared__ float red[8][32];
    __shared__ __align__(16) float comb[64][24];     // phase 2: [input(16) | u(8)]
    __shared__ float sm_part[8][32][4];              // phase 2 readout partials

    // ===================== Phase 1: u partials ============================
    {
        const int bg = blockIdx.x >> 1;          // 0..127 -> 4 batch rows
        const int half = blockIdx.x & 1;         // H-half
        const int bbase = bg * 4;

        float acc[32];
#pragma unroll
        for (int i = 0; i < 32; i++) acc[i] = 0.0f;

#pragma unroll
        for (int it = 0; it < 4; it++) {
            const int j = half * 4096 + it * 1024 + t * 4;
            float4 h4[4];
#pragma unroll
            for (int bl = 0; bl < 4; bl++)
                h4[bl] = *(const float4*)(hidden + (bbase + bl) * HID + j);
            float th[4][4];
#pragma unroll
            for (int bl = 0; bl < 4; bl++) {
                th[bl][0] = __tanhf(h4[bl].x);
                th[bl][1] = __tanhf(h4[bl].y);
                th[bl][2] = __tanhf(h4[bl].z);
                th[bl][3] = __tanhf(h4[bl].w);
            }
#pragma unroll
            for (int r = 0; r < 8; r++) {
                float4 rv = *(const float4*)(R + r * HID + j);
#pragma unroll
                for (int bl = 0; bl < 4; bl++) {
                    float a = acc[bl * 8 + r];
                    a = fmaf(th[bl][0], rv.x, a);
                    a = fmaf(th[bl][1], rv.y, a);
                    a = fmaf(th[bl][2], rv.z, a);
                    a = fmaf(th[bl][3], rv.w, a);
                    acc[bl * 8 + r] = a;
                }
            }
        }

        // fold 32 values across lanes: 31 SHFL, lane L ends with total of acc[L]
#pragma unroll
        for (int m = 16; m >= 1; m >>= 1) {
            const bool up = (lane & m) != 0;
#pragma unroll
            for (int i = 0; i < m; i++) {
                float send = up ? acc[i] : acc[i + m];
                float got = __shfl_xor_sync(0xffffffffu, send, m);
                acc[i] = (up ? acc[i + m] : acc[i]) + got;
            }
        }
        red[w][lane] = acc[0];
        __syncthreads();
        if (t < 32) {
            float s = 0.0f;
#pragma unroll
            for (int w2 = 0; w2 < 8; w2++) s += red[w2][t];
            g_u_part[half][bbase * RANK + t] = s;   // L -> (bbase + L>>3)*8 + (L&7)
        }
    }

    grid_barrier();

    // ============ Phase 2: new_h + fused readout partials =================
    {
        const int jt = blockIdx.x & 31;          // 32 j-tiles of 256
        const int bc = blockIdx.x >> 5;          // 8 batch chunks of 64
        const int b0 = bc * 64;
        const int jg = t & 127;                  // 128 groups of 2 j
        const int bs = t >> 7;                   // 0..1 (warps 0-3 / 4-7)
        const int j0 = jt * 256 + jg * 2;

        // stage [input | u] per batch row: comb[bi][0..15]=input, [16..23]=u
        for (int v = t; v < 64 * 24; v += TPB) {
            const int bi = v / 24, c = v - bi * 24;
            float val;
            if (c < NIN) {
                val = input[(b0 + bi) * NIN + c];
            } else {
                const int idx = (b0 + bi) * RANK + (c - NIN);
                val = (g_u_part[0][idx] + g_u_part[1][idx]) * (1.0f / (float)HID);
            }
            comb[bi][c] = val;
        }

        ull wj[2][8];
        ull lj[2][4];
        float wo[2][4];   // Wout for this thread's 2 j-columns
#pragma unroll
        for (int jj = 0; jj < 2; jj++) {
            const ull* wr = (const ull*)(Win + (j0 + jj) * NIN);
#pragma unroll
            for (int i = 0; i < 8; i++) wj[jj][i] = wr[i];
            const ull* lr = (const ull*)(L + (j0 + jj) * RANK);
#pragma unroll
            for (int r = 0; r < 4; r++) lj[jj][r] = lr[r];
#pragma unroll
            for (int o = 0; o < 4; o++) wo[jj][o] = Wout[o * HID + j0 + jj];
        }
        __syncthreads();

#pragma unroll 4
        for (int bi = bs; bi < 64; bi += 2) {
            const int b = b0 + bi;

            // 6x LDS.128 broadcast: 24 floats = 12 f32x2 operand pairs
            union { float4 f4[6]; ull p[12]; } cb;
            const float4* cp = (const float4*)&comb[bi][0];
#pragma unroll
            for (int q = 0; q < 6; q++) cb.f4[q] = cp[q];

            float2 h2 = *(const float2*)(hidden + b * HID + j0);

            float res[2];
#pragma unroll
            for (int jj = 0; jj < 2; jj++) {
                ull acc = 0ULL;
#pragma unroll
                for (int i = 0; i < 8; i++) ffma2(acc, wj[jj][i], cb.p[i]);
#pragma unroll
                for (int r = 0; r < 4; r++) ffma2(acc, lj[jj][r], cb.p[8 + r]);
                float lo, hi;
                unpack2(lo, hi, acc);
                res[jj] = lo + hi;
            }

            float2 o2;
            o2.x = fmaf(0.1f, res[0], 0.9f * h2.x);
            o2.y = fmaf(0.1f, res[1], 0.9f * h2.y);
            *(float2*)(nh + b * HID + j0) = o2;

            // fused readout: acc4[o] = tanh(nh0)*wo0[o] + tanh(nh1)*wo1[o]
            const float t0 = __tanhf(o2.x), t1 = __tanhf(o2.y);
            float acc4[4];
#pragma unroll
            for (int o = 0; o < 4; o++)
                acc4[o] = fmaf(t0, wo[0][o], t1 * wo[1][o]);

            // fold 4 values over lane bits 0,1 then reduce bits 2,3,4
#pragma unroll
            for (int m = 2; m >= 1; m >>= 1) {
                const bool up = (lane & m) != 0;
#pragma unroll
                for (int i = 0; i < m; i++) {
                    float send = up ? acc4[i] : acc4[i + m];
                    float got = __shfl_xor_sync(0xffffffffu, send, m);
                    acc4[i] = (up ? acc4[i + m] : acc4[i]) + got;
                }
            }
            acc4[0] += __shfl_xor_sync(0xffffffffu, acc4[0], 4);
            acc4[0] += __shfl_xor_sync(0xffffffffu, acc4[0], 8);
            acc4[0] += __shfl_xor_sync(0xffffffffu, acc4[0], 16);
            if (lane < 4) sm_part[w][bi >> 1][lane] = acc4[0];
        }
        __syncthreads();

        // cross-warp fold: (bi,o) over the 4 warps of its half -> g_out_part
        if (t < 64 * 4 / 1) {   // t in [0,256): one (bi,o) each
            const int bi = t >> 2, o = t & 3;
            const int wbase = (bi & 1) ? 4 : 0;
            const int k = bi >> 1;
            float s = sm_part[wbase][k][o] + sm_part[wbase + 1][k][o]
                    + sm_part[wbase + 2][k][o] + sm_part[wbase + 3][k][o];
            g_out_part[jt][(b0 + bi) * NOUT + o] = s;
        }
    }

    grid_barrier();

    // ============ Phase 3: tiny final fold (blocks 0-7) ===================
    {
        const int idx = blockIdx.x * TPB + t;
        if (idx < BATCH * NOUT) {
            float s = 0.0f;
#pragma unroll
            for (int jt = 0; jt < 32; jt++) s += g_out_part[jt][idx];
            out[idx] = s * (1.0f / (float)HID);
        }
    }
}

extern "C" void kernel_launch(void* const* d_in, const int* in_sizes, int n_in,
                              void* d_out, int out_size) {
    const float* input  = (const float*)d_in[0];  // [512,16]
    const float* hidden = (const float*)d_in[1];  // [512,8192]
    const float* Win    = (const float*)d_in[2];  // [8192,16]
    const float* L      = (const float*)d_in[3];  // [8192,8]
    const float* R      = (const float*)d_in[4];  // [8,8192]
    const float* Wout   = (const float*)d_in[5];  // [4,8192]

    float* out = (float*)d_out;                   // [512,4] then [512,8192]
    float* nh  = out + BATCH * NOUT;

    k_fused<<<GRID, TPB>>>(input, hidden, Win, L, R, Wout, nh, out);
}